// round 5
// baseline (speedup 1.0000x reference)
#include <cuda_runtime.h>
#include <cstdint>

#define B  8
#define N  4096
#define F  128
#define GS 1024

#define NBUF 3
#define LOOK 2
#define CPB  74                  // CTAs per batch in gather
#define GATHER_GRID (B * CPB)    // 592

// Scratch
__device__ unsigned int g_keys[B * N];    // monotone-mapped values
__device__ unsigned int g_hist[B * 256];  // top-8-bit histogram (zeroed by select_rank each run)
__device__ int          g_idx[B * GS];    // final top-k indices, jax order

__device__ __forceinline__ unsigned int monot(float v) {
    unsigned int u = __float_as_uint(v);
    return (u & 0x80000000u) ? ~u : (u | 0x80000000u); // bigger float -> bigger uint
}

// ---------------------------------------------------------------------------
// K1: chip-wide extract + per-batch 256-bin histogram of the top 8 key bits.
// 16 CTAs per batch (256 elems each). g_hist must be zero on entry (module
// load zero-init; select_rank_kernel re-zeroes after reading each run).
// ---------------------------------------------------------------------------
__global__ __launch_bounds__(256) void extract_hist_kernel(const float* __restrict__ x)
{
    __shared__ unsigned int h[256];
    const int tid = threadIdx.x;
    h[tid] = 0;
    __syncthreads();

    const int i = blockIdx.x * 256 + tid;   // 0 .. B*N-1 (CTA within one batch)
    const int b = i >> 12;
    unsigned int u = monot(x[(size_t)i * F + (F - 1)]);
    g_keys[i] = u;
    atomicAdd(&h[u >> 24], 1u);
    __syncthreads();

    unsigned int c = h[tid];
    if (c) atomicAdd(&g_hist[b * 256 + tid], c);
}

// ---------------------------------------------------------------------------
// K3: per-batch (8 CTAs, 1024 thr): threshold bin from histogram, candidate
// compaction, 5-pass radix finish on candidates, exact top-GS compaction,
// fused rank-by-count -> ordered g_idx.
// composite key = (u << 12) | (4095 - i): larger composite == earlier in
// jax.lax.top_k order (value desc, tie -> smaller index). Keys unique.
// ---------------------------------------------------------------------------
__device__ unsigned int sh_bin_res, sh_above_res;

__device__ __forceinline__ void scan_hist(const unsigned int* hist, unsigned int need,
                                          unsigned int* s_bin, unsigned int* s_above)
{
    const int tid = threadIdx.x;
    if (tid < 32) {
        unsigned int sum = 0;
        #pragma unroll
        for (int j = 0; j < 8; ++j) sum += hist[tid * 8 + j];
        unsigned int acc = sum;
        #pragma unroll
        for (int off = 1; off < 32; off <<= 1) {
            unsigned int t = __shfl_down_sync(0xFFFFFFFFu, acc, off);
            if (tid + off < 32) acc += t;
        }
        unsigned int running = acc - sum;      // strictly above my 8-bin group
        #pragma unroll
        for (int j = 7; j >= 0; --j) {
            unsigned int c = hist[tid * 8 + j];
            if (running < need && need <= running + c) {
                *s_bin = (unsigned int)(tid * 8 + j);
                *s_above = running;
            }
            running += c;
        }
    }
}

__global__ __launch_bounds__(1024) void select_rank_kernel()
{
    __shared__ unsigned long long cand[N];                       // 32 KB
    __shared__ __align__(16) unsigned long long ssel[GS];        // 8 KB
    __shared__ unsigned int hist[256];
    __shared__ unsigned int s_bin, s_above, s_m, s_cnt;

    const int b   = blockIdx.x;
    const int tid = threadIdx.x;

    if (tid < 256) { hist[tid] = g_hist[b * 256 + tid]; g_hist[b * 256 + tid] = 0; }
    if (tid == 0) { s_m = 0; s_cnt = 0; }
    __syncthreads();

    scan_hist(hist, GS, &s_bin, &s_above);
    __syncthreads();
    const unsigned int bin1 = s_bin;
    unsigned int need = GS - s_above;

    // Build composites (4/thread, coalesced), compact threshold-bin candidates
    unsigned long long comp[4];
    #pragma unroll
    for (int l = 0; l < 4; ++l) {
        int i = l * 1024 + tid;
        unsigned int u = g_keys[b * N + i];
        comp[l] = ((unsigned long long)u << 12) | (unsigned int)(N - 1 - i);
        if ((u >> 24) == bin1) {
            unsigned int p = atomicAdd(&s_m, 1u);
            cand[p] = comp[l];
        }
    }
    __syncthreads();
    const unsigned int m = s_m;

    unsigned long long prefix = (unsigned long long)bin1 << 36;
    unsigned long long pmask  = 0xFFull << 36;

    #pragma unroll
    for (int pass = 0; pass < 5; ++pass) {
        const int          shift = (pass < 4) ? (28 - 8 * pass) : 0;
        const unsigned int dmask = (pass < 4) ? 0xFFu : 0xFu;

        if (tid < 256) hist[tid] = 0;
        __syncthreads();
        for (unsigned int idx = tid; idx < m; idx += 1024) {
            unsigned long long k = cand[idx];
            if ((k & pmask) == prefix)
                atomicAdd(&hist[(unsigned int)(k >> shift) & dmask], 1u);
        }
        __syncthreads();
        scan_hist(hist, need, &s_bin, &s_above);
        __syncthreads();
        prefix |= ((unsigned long long)s_bin) << shift;
        pmask  |= ((unsigned long long)dmask) << shift;
        need   -= s_above;
        __syncthreads();
    }
    // prefix == exact GS-th largest composite. Selected: composite >= prefix.

    #pragma unroll
    for (int l = 0; l < 4; ++l) {
        if (comp[l] >= prefix) {
            unsigned int p = atomicAdd(&s_cnt, 1u);
            ssel[p] = comp[l];
        }
    }
    __syncthreads();

    // Fused rank-by-count (unique keys => unique ranks)
    const unsigned long long mine = ssel[tid];
    const ulonglong2* p2 = (const ulonglong2*)ssel;
    int rank = 0;
    #pragma unroll 4
    for (int j = 0; j < GS / 2; ++j) {
        ulonglong2 v = p2[j];
        rank += (v.x > mine) + (v.y > mine);
    }
    g_idx[b * GS + rank] = (N - 1) - (int)(mine & 0xFFFull);
}

// ---------------------------------------------------------------------------
// Gather: persistent CTAs, cp.async.bulk producer + LDS/STG consumer,
// NBUF smem buffers, lookahead LOOK. One buffer = A row (16KB) + x row (512B).
// ---------------------------------------------------------------------------
__device__ __forceinline__ unsigned int smem_u32(const void* p) {
    return (unsigned int)__cvta_generic_to_shared(p);
}
__device__ __forceinline__ void mbar_init(unsigned int mb, unsigned int cnt) {
    asm volatile("mbarrier.init.shared.b64 [%0], %1;" :: "r"(mb), "r"(cnt) : "memory");
}
__device__ __forceinline__ void mbar_expect_tx(unsigned int mb, unsigned int bytes) {
    asm volatile("mbarrier.arrive.expect_tx.shared.b64 _, [%0], %1;"
                 :: "r"(mb), "r"(bytes) : "memory");
}
__device__ __forceinline__ void bulk_g2s(unsigned int dst, const void* src,
                                         unsigned int bytes, unsigned int mb) {
    asm volatile("cp.async.bulk.shared::cta.global.mbarrier::complete_tx::bytes "
                 "[%0], [%1], %2, [%3];"
                 :: "r"(dst), "l"(src), "r"(bytes), "r"(mb) : "memory");
}
__device__ __forceinline__ void mbar_wait(unsigned int mb, unsigned int parity) {
    asm volatile(
        "{\n\t.reg .pred P;\n\t"
        "WL_%=:\n\t"
        "mbarrier.try_wait.parity.acquire.cta.shared::cta.b64 P, [%0], %1, 0x989680;\n\t"
        "@!P bra WL_%=;\n\t"
        "}" :: "r"(mb), "r"(parity) : "memory");
}
__device__ __forceinline__ void fence_async() {
    asm volatile("fence.proxy.async.shared::cta;" ::: "memory");
}

#define BUF_ELEMS (N + F)
#define SMEM_GATHER (64 + GS * 4 + NBUF * BUF_ELEMS * 4)

__global__ __launch_bounds__(512) void gather_kernel(const float* __restrict__ A,
                                                     const float* __restrict__ x,
                                                     float* __restrict__ out)
{
    extern __shared__ unsigned char smem_raw[];
    unsigned long long* mbar = (unsigned long long*)smem_raw;         // NBUF x 8B
    int*   sidx = (int*)(smem_raw + 64);                              // 4 KB
    float* bufs = (float*)(smem_raw + 64 + GS * 4);                   // NBUF x 16.5KB

    const int tid = threadIdx.x;
    const int b   = blockIdx.x & 7;          // batch
    const int c   = blockIdx.x >> 3;         // 0..CPB-1
    const int cnt = (GS - 1 - c) / CPB + 1;  // rows this CTA handles (13/14)

    for (int t = tid; t < GS; t += 512) sidx[t] = g_idx[b * GS + t];
    if (tid == 0) {
        #pragma unroll
        for (int s = 0; s < NBUF; ++s) mbar_init(smem_u32(&mbar[s]), 1);
        fence_async();
    }
    __syncthreads();

    const float* Ab = A + (size_t)b * N * N;
    const float* xb = x + (size_t)b * N * F;

    // producer helper: issue row k of this CTA into buffer k%NBUF
    auto issue = [&](int k) {
        const int l  = c + k * CPB;
        const int ri = sidx[l];
        unsigned int mb = smem_u32(&mbar[k % NBUF]);
        float* buf = bufs + (k % NBUF) * BUF_ELEMS;
        mbar_expect_tx(mb, BUF_ELEMS * 4);
        bulk_g2s(smem_u32(buf),     Ab + (size_t)ri * N, N * 4, mb);
        bulk_g2s(smem_u32(buf + N), xb + (size_t)ri * F, F * 4, mb);
    };

    if (tid == 0) {
        for (int k = 0; k < LOOK && k < cnt; ++k) issue(k);
    }

    for (int k = 0; k < cnt; ++k) {
        if (tid == 0 && k + LOOK < cnt) { fence_async(); issue(k + LOOK); }

        mbar_wait(smem_u32(&mbar[k % NBUF]), (k / NBUF) & 1);

        const float* buf = bufs + (k % NBUF) * BUF_ELEMS;
        const int l = c + k * CPB;

        float* orow = out + ((size_t)b * GS + l) * GS;
        orow[tid]       = buf[sidx[tid]];
        orow[tid + 512] = buf[sidx[tid + 512]];

        if (tid < F / 4) {
            ((float4*)(out + (size_t)B * GS * GS + ((size_t)b * GS + l) * F))[tid]
                = ((const float4*)(buf + N))[tid];
        }
        __syncthreads();   // buffer k%NBUF free for reuse
    }
}

// ---------------------------------------------------------------------------
extern "C" void kernel_launch(void* const* d_in, const int* in_sizes, int n_in,
                              void* d_out, int out_size)
{
    const float* A = (const float*)d_in[0];  // (8,4096,4096) f32
    const float* x = (const float*)d_in[1];  // (8,4096,128)  f32
    float* out = (float*)d_out;              // At2 (8,1024,1024) ++ xg (8,1024,128)

    cudaFuncSetAttribute(gather_kernel,
                         cudaFuncAttributeMaxDynamicSharedMemorySize, SMEM_GATHER);

    extract_hist_kernel<<<(B * N) / 256, 256>>>(x);
    select_rank_kernel<<<B, 1024>>>();
    gather_kernel<<<GATHER_GRID, 512, SMEM_GATHER>>>(A, x, out);
}

// round 6
// speedup vs baseline: 1.0331x; 1.0331x over previous
#include <cuda_runtime.h>
#include <cstdint>

#define B  8
#define N  4096
#define F  128
#define GS 1024

// Scratch
__device__ unsigned int g_keys[B * N];    // monotone-mapped values
__device__ unsigned int g_hist[B * 256];  // top-8-bit histogram (re-zeroed by select_rank)
__device__ int          g_idx[B * GS];    // final top-k indices, jax order

__device__ __forceinline__ unsigned int monot(float v) {
    unsigned int u = __float_as_uint(v);
    return (u & 0x80000000u) ? ~u : (u | 0x80000000u); // bigger float -> bigger uint
}

// ---------------------------------------------------------------------------
// K1: chip-wide extract + per-batch 256-bin histogram of the top 8 key bits.
// g_hist zero on entry (module zero-init; select_rank re-zeroes each run).
// ---------------------------------------------------------------------------
__global__ __launch_bounds__(256) void extract_hist_kernel(const float* __restrict__ x)
{
    __shared__ unsigned int h[256];
    const int tid = threadIdx.x;
    h[tid] = 0;
    __syncthreads();

    const int i = blockIdx.x * 256 + tid;   // 0 .. B*N-1
    const int b = i >> 12;
    unsigned int u = monot(x[(size_t)i * F + (F - 1)]);
    g_keys[i] = u;
    atomicAdd(&h[u >> 24], 1u);
    __syncthreads();

    unsigned int c = h[tid];
    if (c) atomicAdd(&g_hist[b * 256 + tid], c);
}

// ---------------------------------------------------------------------------
// K2: per-batch: threshold bin from histogram, candidate compaction,
// 5-pass radix finish on candidates, exact top-GS compaction, fused
// rank-by-count -> ordered g_idx.
// composite = (u << 12) | (4095 - i): larger == earlier in jax order.
// ---------------------------------------------------------------------------
__device__ __forceinline__ void scan_hist(const unsigned int* hist, unsigned int need,
                                          unsigned int* s_bin, unsigned int* s_above)
{
    const int tid = threadIdx.x;
    if (tid < 32) {
        unsigned int sum = 0;
        #pragma unroll
        for (int j = 0; j < 8; ++j) sum += hist[tid * 8 + j];
        unsigned int acc = sum;
        #pragma unroll
        for (int off = 1; off < 32; off <<= 1) {
            unsigned int t = __shfl_down_sync(0xFFFFFFFFu, acc, off);
            if (tid + off < 32) acc += t;
        }
        unsigned int running = acc - sum;      // strictly above my 8-bin group
        #pragma unroll
        for (int j = 7; j >= 0; --j) {
            unsigned int c = hist[tid * 8 + j];
            if (running < need && need <= running + c) {
                *s_bin = (unsigned int)(tid * 8 + j);
                *s_above = running;
            }
            running += c;
        }
    }
}

__global__ __launch_bounds__(1024) void select_rank_kernel()
{
    __shared__ unsigned long long cand[N];                       // 32 KB
    __shared__ __align__(16) unsigned long long ssel[GS];        // 8 KB
    __shared__ unsigned int hist[256];
    __shared__ unsigned int s_bin, s_above, s_m, s_cnt;

    const int b   = blockIdx.x;
    const int tid = threadIdx.x;

    if (tid < 256) { hist[tid] = g_hist[b * 256 + tid]; g_hist[b * 256 + tid] = 0; }
    if (tid == 0) { s_m = 0; s_cnt = 0; }
    __syncthreads();

    scan_hist(hist, GS, &s_bin, &s_above);
    __syncthreads();
    const unsigned int bin1 = s_bin;
    unsigned int need = GS - s_above;

    unsigned long long comp[4];
    #pragma unroll
    for (int l = 0; l < 4; ++l) {
        int i = l * 1024 + tid;
        unsigned int u = g_keys[b * N + i];
        comp[l] = ((unsigned long long)u << 12) | (unsigned int)(N - 1 - i);
        if ((u >> 24) == bin1) {
            unsigned int p = atomicAdd(&s_m, 1u);
            cand[p] = comp[l];
        }
    }
    __syncthreads();
    const unsigned int m = s_m;

    unsigned long long prefix = (unsigned long long)bin1 << 36;
    unsigned long long pmask  = 0xFFull << 36;

    #pragma unroll
    for (int pass = 0; pass < 5; ++pass) {
        const int          shift = (pass < 4) ? (28 - 8 * pass) : 0;
        const unsigned int dmask = (pass < 4) ? 0xFFu : 0xFu;

        if (tid < 256) hist[tid] = 0;
        __syncthreads();
        for (unsigned int idx = tid; idx < m; idx += 1024) {
            unsigned long long k = cand[idx];
            if ((k & pmask) == prefix)
                atomicAdd(&hist[(unsigned int)(k >> shift) & dmask], 1u);
        }
        __syncthreads();
        scan_hist(hist, need, &s_bin, &s_above);
        __syncthreads();
        prefix |= ((unsigned long long)s_bin) << shift;
        pmask  |= ((unsigned long long)dmask) << shift;
        need   -= s_above;
        __syncthreads();
    }

    #pragma unroll
    for (int l = 0; l < 4; ++l) {
        if (comp[l] >= prefix) {
            unsigned int p = atomicAdd(&s_cnt, 1u);
            ssel[p] = comp[l];
        }
    }
    __syncthreads();

    const unsigned long long mine = ssel[tid];
    const ulonglong2* p2 = (const ulonglong2*)ssel;
    int rank = 0;
    #pragma unroll 4
    for (int j = 0; j < GS / 2; ++j) {
        ulonglong2 v = p2[j];
        rank += (v.x > mine) + (v.y > mine);
    }
    g_idx[b * GS + rank] = (N - 1) - (int)(mine & 0xFFFull);
}

// ---------------------------------------------------------------------------
// K3: one CTA per output row. 16KB A row + 512B x row arrive via one
// cp.async.bulk pair into smem (single mbarrier). Column indices are read
// per-thread straight from g_idx (L2-resident). 256 threads, 8 CTAs/SM.
// ---------------------------------------------------------------------------
__device__ __forceinline__ unsigned int smem_u32(const void* p) {
    return (unsigned int)__cvta_generic_to_shared(p);
}

__global__ __launch_bounds__(256) void gather_kernel(const float* __restrict__ A,
                                                     const float* __restrict__ x,
                                                     float* __restrict__ out)
{
    __shared__ __align__(16) float row[N];     // 16 KB
    __shared__ __align__(16) float xrow[F];    // 512 B
    __shared__ __align__(8)  unsigned long long mbar;

    const int bi  = blockIdx.x;
    const int b   = bi >> 10;
    const int i   = bi & (GS - 1);
    const int tid = threadIdx.x;

    // Per-thread column indices (own lanes only -> no smem stage, no sync)
    const int* gi = g_idx + b * GS;
    const int ci0 = gi[tid];
    const int ci1 = gi[tid + 256];
    const int ci2 = gi[tid + 512];
    const int ci3 = gi[tid + 768];

    if (tid == 0) {
        asm volatile("mbarrier.init.shared.b64 [%0], 1;"
                     :: "r"(smem_u32(&mbar)) : "memory");
        asm volatile("fence.proxy.async.shared::cta;" ::: "memory");
    }
    __syncthreads();

    if (tid == 0) {
        const int ri = gi[i];
        asm volatile("mbarrier.arrive.expect_tx.shared.b64 _, [%0], %1;"
                     :: "r"(smem_u32(&mbar)), "r"((unsigned)((N + F) * 4)) : "memory");
        asm volatile("cp.async.bulk.shared::cta.global.mbarrier::complete_tx::bytes "
                     "[%0], [%1], %2, [%3];"
                     :: "r"(smem_u32(row)),
                        "l"(A + ((size_t)b * N + ri) * N),
                        "r"((unsigned)(N * 4)), "r"(smem_u32(&mbar)) : "memory");
        asm volatile("cp.async.bulk.shared::cta.global.mbarrier::complete_tx::bytes "
                     "[%0], [%1], %2, [%3];"
                     :: "r"(smem_u32(xrow)),
                        "l"(x + ((size_t)b * N + ri) * F),
                        "r"((unsigned)(F * 4)), "r"(smem_u32(&mbar)) : "memory");
    }

    // Wait for bulk completion (phase 0)
    asm volatile(
        "{\n\t.reg .pred P;\n\t"
        "WL_%=:\n\t"
        "mbarrier.try_wait.parity.acquire.cta.shared::cta.b64 P, [%0], 0, 0x989680;\n\t"
        "@!P bra WL_%=;\n\t"
        "}" :: "r"(smem_u32(&mbar)) : "memory");

    float* orow = out + ((size_t)b * GS + i) * GS;
    orow[tid]       = row[ci0];
    orow[tid + 256] = row[ci1];
    orow[tid + 512] = row[ci2];
    orow[tid + 768] = row[ci3];

    if (tid < F / 4) {
        ((float4*)(out + (size_t)B * GS * GS + ((size_t)b * GS + i) * F))[tid]
            = ((const float4*)xrow)[tid];
    }
}

// ---------------------------------------------------------------------------
extern "C" void kernel_launch(void* const* d_in, const int* in_sizes, int n_in,
                              void* d_out, int out_size)
{
    const float* A = (const float*)d_in[0];  // (8,4096,4096) f32
    const float* x = (const float*)d_in[1];  // (8,4096,128)  f32
    float* out = (float*)d_out;              // At2 (8,1024,1024) ++ xg (8,1024,128)

    extract_hist_kernel<<<(B * N) / 256, 256>>>(x);
    select_rank_kernel<<<B, 1024>>>();
    gather_kernel<<<B * GS, 256>>>(A, x, out);
}